// round 14
// baseline (speedup 1.0000x reference)
#include <cuda_runtime.h>

#define OBS_DIM   256
#define HID_DIM   512
#define ACT_DIM   18
#define BATCH     1024
#define ETA       0.01f
#define LAMBDA    0.95f

__global__ void q_init_kernel(const float* __restrict__ bq, float* __restrict__ q) {
    int i = blockIdx.x * blockDim.x + threadIdx.x;
    if (i < BATCH * ACT_DIM) q[i] = bq[i % ACT_DIM];
}

__device__ __forceinline__ float tanh_approx(float x) {
    float r;
    asm("tanh.approx.f32 %0, %1;" : "=f"(r) : "f"(x));
    return r;
}

// Fused MPN step + Hebbian update + q-head. R8 warp body (measured best:
// 155.3us, DRAM 83.3%) with 512-thread blocks: 16 warps = 16 h-rows per
// (batch, block). Same per-warp dataflow and register schedule; half the
// blocks, half the epilogue instances and q-REDs. Epilogue barrier split
// arrive/sync so warps 1-15 retire right after their M stores.
__global__ __launch_bounds__(512) void mpn_step_kernel(
    const float* __restrict__ obs,
    const float* __restrict__ M,
    const float* __restrict__ W,
    const float* __restrict__ bh,
    const float* __restrict__ Wq,
    float* __restrict__ newM,
    float* __restrict__ q)
{
    __shared__ float hsh[16];           // hv per warp

    const int b     = blockIdx.x;       // batch-major: W stays L1-hot per wave
    const int hbase = blockIdx.y * 16;
    const int tid   = threadIdx.x;
    const int warp  = tid >> 5;
    const int lane  = tid & 31;
    const int h     = hbase + warp;

    const float4* xp = reinterpret_cast<const float4*>(obs + (size_t)b * OBS_DIM);
    const float4* wp = reinterpret_cast<const float4*>(W + (size_t)h * OBS_DIM);
    const float4* Mrow = reinterpret_cast<const float4*>(
        M + ((size_t)b * HID_DIM + h) * OBS_DIM);

    // Independent loads, issued back-to-back: M streams (evict-first),
    // W/obs cache-resident.
    const float4 m0 = __ldcs(Mrow + lane);
    const float4 m1 = __ldcs(Mrow + lane + 32);
    const float4 w0 = __ldg(wp + lane);
    const float4 w1 = __ldg(wp + lane + 32);
    const float4 x0 = __ldg(xp + lane);
    const float4 x1 = __ldg(xp + lane + 32);

    // sum_o W[h,o] * obs[b,o] * (1 + M[b,h,o])
    float acc =
        w0.x * x0.x * (1.0f + m0.x) + w0.y * x0.y * (1.0f + m0.y) +
        w0.z * x0.z * (1.0f + m0.z) + w0.w * x0.w * (1.0f + m0.w) +
        w1.x * x1.x * (1.0f + m1.x) + w1.y * x1.y * (1.0f + m1.y) +
        w1.z * x1.z * (1.0f + m1.z) + w1.w * x1.w * (1.0f + m1.w);

    #pragma unroll
    for (int o = 16; o; o >>= 1)
        acc += __shfl_xor_sync(0xffffffffu, acc, o);

    const float hv = tanh_approx(acc + __ldg(bh + h));
    const float eh = ETA * hv;

    float4 n0, n1;
    n0.x = LAMBDA * m0.x + eh * x0.x;  n0.y = LAMBDA * m0.y + eh * x0.y;
    n0.z = LAMBDA * m0.z + eh * x0.z;  n0.w = LAMBDA * m0.w + eh * x0.w;
    n1.x = LAMBDA * m1.x + eh * x1.x;  n1.y = LAMBDA * m1.y + eh * x1.y;
    n1.z = LAMBDA * m1.z + eh * x1.z;  n1.w = LAMBDA * m1.w + eh * x1.w;

    float4* out = reinterpret_cast<float4*>(
        newM + ((size_t)b * HID_DIM + h) * OBS_DIM);
    __stcs(out + lane,      n0);
    __stcs(out + lane + 32, n1);

    if (lane == 0) hsh[warp] = hv;

    if (warp != 0) {
        // Producers: signal and retire. No blocking wait.
        asm volatile("bar.arrive 1, 512;");
        return;
    }
    asm volatile("bar.sync 1, 512;");

    // q-head epilogue: warp 0 reduces this block's 16 h-rows, 18 REDs total.
    if (lane < ACT_DIM) {
        const float4* wq = reinterpret_cast<const float4*>(
            Wq + (size_t)lane * HID_DIM + hbase);
        const float4 a0 = __ldg(wq);      // L1-hot: same hbase for the wave
        const float4 a1 = __ldg(wq + 1);
        const float4 a2 = __ldg(wq + 2);
        const float4 a3 = __ldg(wq + 3);
        const float qv = a0.x * hsh[0]  + a0.y * hsh[1]
                       + a0.z * hsh[2]  + a0.w * hsh[3]
                       + a1.x * hsh[4]  + a1.y * hsh[5]
                       + a1.z * hsh[6]  + a1.w * hsh[7]
                       + a2.x * hsh[8]  + a2.y * hsh[9]
                       + a2.z * hsh[10] + a2.w * hsh[11]
                       + a3.x * hsh[12] + a3.y * hsh[13]
                       + a3.z * hsh[14] + a3.w * hsh[15];
        atomicAdd(q + (size_t)b * ACT_DIM + lane, qv);
    }
}

extern "C" void kernel_launch(void* const* d_in, const int* in_sizes, int n_in,
                              void* d_out, int out_size) {
    const float* obs = (const float*)d_in[0];  // [1024, 256]
    const float* M   = (const float*)d_in[1];  // [1024, 512, 256]
    const float* W   = (const float*)d_in[2];  // [512, 256]
    const float* bh  = (const float*)d_in[3];  // [512]
    const float* Wq  = (const float*)d_in[4];  // [18, 512]
    const float* bq  = (const float*)d_in[5];  // [18]

    float* q    = (float*)d_out;               // [1024, 18]
    float* newM = q + (size_t)BATCH * ACT_DIM; // [1024, 512, 256]

    q_init_kernel<<<(BATCH * ACT_DIM + 255) / 256, 256>>>(bq, q);

    dim3 grid(BATCH, HID_DIM / 16);            // batch-major for W reuse
    mpn_step_kernel<<<grid, 512>>>(obs, M, W, bh, Wq, newM, q);
}

// round 15
// speedup vs baseline: 1.0624x; 1.0624x over previous
#include <cuda_runtime.h>

#define OBS_DIM   256
#define HID_DIM   512
#define ACT_DIM   18
#define BATCH     1024
#define ETA       0.01f
#define LAMBDA    0.95f

__global__ void q_init_kernel(const float* __restrict__ bq, float* __restrict__ q) {
    int i = blockIdx.x * blockDim.x + threadIdx.x;
    if (i < BATCH * ACT_DIM) q[i] = bq[i % ACT_DIM];
}

__device__ __forceinline__ float tanh_approx(float x) {
    float r;
    asm("tanh.approx.f32 %0, %1;" : "=f"(r) : "f"(x));
    return r;
}

// Fused MPN step + Hebbian update + q-head. One (batch, 8 h-rows) per block;
// each warp is a fully independent load->reduce->store chain: obs/W/Wq come
// straight from L1/L2 via __ldg (obs is 1MB total, L2-resident; W slice
// shared by the whole wave), so there is NO entry barrier. The only barrier
// is the q-head epilogue, split arrive/sync so warps 1-7 retire immediately
// after their M stores. Measured: 155.3us kernel, DRAM 83.3% (6.6 TB/s) -
// best of 9 structural variants; M is read and written exactly once.
__global__ __launch_bounds__(256) void mpn_step_kernel(
    const float* __restrict__ obs,
    const float* __restrict__ M,
    const float* __restrict__ W,
    const float* __restrict__ bh,
    const float* __restrict__ Wq,
    float* __restrict__ newM,
    float* __restrict__ q)
{
    __shared__ float hsh[8];            // hv per warp

    const int b     = blockIdx.x;       // batch-major: W stays L1-hot per wave
    const int hbase = blockIdx.y * 8;
    const int tid   = threadIdx.x;
    const int warp  = tid >> 5;
    const int lane  = tid & 31;
    const int h     = hbase + warp;

    const float4* xp = reinterpret_cast<const float4*>(obs + (size_t)b * OBS_DIM);
    const float4* wp = reinterpret_cast<const float4*>(W + (size_t)h * OBS_DIM);
    const float4* Mrow = reinterpret_cast<const float4*>(
        M + ((size_t)b * HID_DIM + h) * OBS_DIM);

    // Independent loads, issued back-to-back: M streams (evict-first),
    // W/obs cache-resident.
    const float4 m0 = __ldcs(Mrow + lane);
    const float4 m1 = __ldcs(Mrow + lane + 32);
    const float4 w0 = __ldg(wp + lane);
    const float4 w1 = __ldg(wp + lane + 32);
    const float4 x0 = __ldg(xp + lane);
    const float4 x1 = __ldg(xp + lane + 32);

    // sum_o W[h,o] * obs[b,o] * (1 + M[b,h,o])
    float acc =
        w0.x * x0.x * (1.0f + m0.x) + w0.y * x0.y * (1.0f + m0.y) +
        w0.z * x0.z * (1.0f + m0.z) + w0.w * x0.w * (1.0f + m0.w) +
        w1.x * x1.x * (1.0f + m1.x) + w1.y * x1.y * (1.0f + m1.y) +
        w1.z * x1.z * (1.0f + m1.z) + w1.w * x1.w * (1.0f + m1.w);

    #pragma unroll
    for (int o = 16; o; o >>= 1)
        acc += __shfl_xor_sync(0xffffffffu, acc, o);

    const float hv = tanh_approx(acc + __ldg(bh + h));
    const float eh = ETA * hv;

    float4 n0, n1;
    n0.x = LAMBDA * m0.x + eh * x0.x;  n0.y = LAMBDA * m0.y + eh * x0.y;
    n0.z = LAMBDA * m0.z + eh * x0.z;  n0.w = LAMBDA * m0.w + eh * x0.w;
    n1.x = LAMBDA * m1.x + eh * x1.x;  n1.y = LAMBDA * m1.y + eh * x1.y;
    n1.z = LAMBDA * m1.z + eh * x1.z;  n1.w = LAMBDA * m1.w + eh * x1.w;

    float4* out = reinterpret_cast<float4*>(
        newM + ((size_t)b * HID_DIM + h) * OBS_DIM);
    __stcs(out + lane,      n0);
    __stcs(out + lane + 32, n1);

    if (lane == 0) hsh[warp] = hv;

    if (warp != 0) {
        // Producers: signal and retire. No blocking wait.
        asm volatile("bar.arrive 1, 256;");
        return;
    }
    asm volatile("bar.sync 1, 256;");

    // q-head epilogue: warp 0 reduces this block's 8 h-rows, 18 REDs total.
    if (lane < ACT_DIM) {
        const float4* wq = reinterpret_cast<const float4*>(
            Wq + (size_t)lane * HID_DIM + hbase);
        const float4 a0 = __ldg(wq);      // L1-hot: same hbase for the wave
        const float4 a1 = __ldg(wq + 1);
        const float qv = a0.x * hsh[0] + a0.y * hsh[1]
                       + a0.z * hsh[2] + a0.w * hsh[3]
                       + a1.x * hsh[4] + a1.y * hsh[5]
                       + a1.z * hsh[6] + a1.w * hsh[7];
        atomicAdd(q + (size_t)b * ACT_DIM + lane, qv);
    }
}

extern "C" void kernel_launch(void* const* d_in, const int* in_sizes, int n_in,
                              void* d_out, int out_size) {
    const float* obs = (const float*)d_in[0];  // [1024, 256]
    const float* M   = (const float*)d_in[1];  // [1024, 512, 256]
    const float* W   = (const float*)d_in[2];  // [512, 256]
    const float* bh  = (const float*)d_in[3];  // [512]
    const float* Wq  = (const float*)d_in[4];  // [18, 512]
    const float* bq  = (const float*)d_in[5];  // [18]

    float* q    = (float*)d_out;               // [1024, 18]
    float* newM = q + (size_t)BATCH * ACT_DIM; // [1024, 512, 256]

    q_init_kernel<<<(BATCH * ACT_DIM + 255) / 256, 256>>>(bq, q);

    dim3 grid(BATCH, HID_DIM / 8);             // batch-major for W reuse
    mpn_step_kernel<<<grid, 256>>>(obs, M, W, bh, Wq, newM, q);
}

// round 16
// speedup vs baseline: 1.0639x; 1.0014x over previous
#include <cuda_runtime.h>

#define OBS_DIM   256
#define HID_DIM   512
#define ACT_DIM   18
#define BATCH     1024
#define ETA       0.01f
#define LAMBDA    0.95f

__global__ void q_init_kernel(const float* __restrict__ bq, float* __restrict__ q) {
    int i = blockIdx.x * blockDim.x + threadIdx.x;
    if (i < BATCH * ACT_DIM) q[i] = bq[i % ACT_DIM];
}

__device__ __forceinline__ float tanh_approx(float x) {
    float r;
    asm("tanh.approx.f32 %0, %1;" : "=f"(r) : "f"(x));
    return r;
}

// Fused MPN step + Hebbian update + q-head. One (batch, 8 h-rows) per block;
// each warp is a fully independent load->reduce->store chain: obs/W/Wq come
// straight from L1/L2 via __ldg (obs is 1MB total, L2-resident; W slice
// shared by the whole wave), so there is NO entry barrier. The only barrier
// is the q-head epilogue, split arrive/sync so warps 1-7 retire immediately
// after their M stores. M (537MB each way) is read and written exactly once,
// streaming at 82-83% of HBM spec — the measured read/write-turnaround
// ceiling across 10 structural variants. Session-converged optimum.
__global__ __launch_bounds__(256) void mpn_step_kernel(
    const float* __restrict__ obs,
    const float* __restrict__ M,
    const float* __restrict__ W,
    const float* __restrict__ bh,
    const float* __restrict__ Wq,
    float* __restrict__ newM,
    float* __restrict__ q)
{
    __shared__ float hsh[8];            // hv per warp

    const int b     = blockIdx.x;       // batch-major: W stays L1-hot per wave
    const int hbase = blockIdx.y * 8;
    const int tid   = threadIdx.x;
    const int warp  = tid >> 5;
    const int lane  = tid & 31;
    const int h     = hbase + warp;

    const float4* xp = reinterpret_cast<const float4*>(obs + (size_t)b * OBS_DIM);
    const float4* wp = reinterpret_cast<const float4*>(W + (size_t)h * OBS_DIM);
    const float4* Mrow = reinterpret_cast<const float4*>(
        M + ((size_t)b * HID_DIM + h) * OBS_DIM);

    // Independent loads, issued back-to-back: M streams (evict-first),
    // W/obs cache-resident.
    const float4 m0 = __ldcs(Mrow + lane);
    const float4 m1 = __ldcs(Mrow + lane + 32);
    const float4 w0 = __ldg(wp + lane);
    const float4 w1 = __ldg(wp + lane + 32);
    const float4 x0 = __ldg(xp + lane);
    const float4 x1 = __ldg(xp + lane + 32);

    // sum_o W[h,o] * obs[b,o] * (1 + M[b,h,o])
    float acc =
        w0.x * x0.x * (1.0f + m0.x) + w0.y * x0.y * (1.0f + m0.y) +
        w0.z * x0.z * (1.0f + m0.z) + w0.w * x0.w * (1.0f + m0.w) +
        w1.x * x1.x * (1.0f + m1.x) + w1.y * x1.y * (1.0f + m1.y) +
        w1.z * x1.z * (1.0f + m1.z) + w1.w * x1.w * (1.0f + m1.w);

    #pragma unroll
    for (int o = 16; o; o >>= 1)
        acc += __shfl_xor_sync(0xffffffffu, acc, o);

    const float hv = tanh_approx(acc + __ldg(bh + h));
    const float eh = ETA * hv;

    float4 n0, n1;
    n0.x = LAMBDA * m0.x + eh * x0.x;  n0.y = LAMBDA * m0.y + eh * x0.y;
    n0.z = LAMBDA * m0.z + eh * x0.z;  n0.w = LAMBDA * m0.w + eh * x0.w;
    n1.x = LAMBDA * m1.x + eh * x1.x;  n1.y = LAMBDA * m1.y + eh * x1.y;
    n1.z = LAMBDA * m1.z + eh * x1.z;  n1.w = LAMBDA * m1.w + eh * x1.w;

    float4* out = reinterpret_cast<float4*>(
        newM + ((size_t)b * HID_DIM + h) * OBS_DIM);
    __stcs(out + lane,      n0);
    __stcs(out + lane + 32, n1);

    if (lane == 0) hsh[warp] = hv;

    if (warp != 0) {
        // Producers: signal and retire. No blocking wait.
        asm volatile("bar.arrive 1, 256;");
        return;
    }
    asm volatile("bar.sync 1, 256;");

    // q-head epilogue: warp 0 reduces this block's 8 h-rows, 18 REDs total.
    if (lane < ACT_DIM) {
        const float4* wq = reinterpret_cast<const float4*>(
            Wq + (size_t)lane * HID_DIM + hbase);
        const float4 a0 = __ldg(wq);      // L1-hot: same hbase for the wave
        const float4 a1 = __ldg(wq + 1);
        const float qv = a0.x * hsh[0] + a0.y * hsh[1]
                       + a0.z * hsh[2] + a0.w * hsh[3]
                       + a1.x * hsh[4] + a1.y * hsh[5]
                       + a1.z * hsh[6] + a1.w * hsh[7];
        atomicAdd(q + (size_t)b * ACT_DIM + lane, qv);
    }
}

extern "C" void kernel_launch(void* const* d_in, const int* in_sizes, int n_in,
                              void* d_out, int out_size) {
    const float* obs = (const float*)d_in[0];  // [1024, 256]
    const float* M   = (const float*)d_in[1];  // [1024, 512, 256]
    const float* W   = (const float*)d_in[2];  // [512, 256]
    const float* bh  = (const float*)d_in[3];  // [512]
    const float* Wq  = (const float*)d_in[4];  // [18, 512]
    const float* bq  = (const float*)d_in[5];  // [18]

    float* q    = (float*)d_out;               // [1024, 18]
    float* newM = q + (size_t)BATCH * ACT_DIM; // [1024, 512, 256]

    q_init_kernel<<<(BATCH * ACT_DIM + 255) / 256, 256>>>(bq, q);

    dim3 grid(BATCH, HID_DIM / 8);             // batch-major for W reuse
    mpn_step_kernel<<<grid, 256>>>(obs, M, W, bh, Wq, newM, q);
}

// round 17
// speedup vs baseline: 1.0891x; 1.0238x over previous
#include <cuda_runtime.h>

#define OBS_DIM   256
#define HID_DIM   512
#define ACT_DIM   18
#define BATCH     1024
#define ETA       0.01f
#define LAMBDA    0.95f

__global__ void q_init_kernel(const float* __restrict__ bq, float* __restrict__ q) {
    int i = blockIdx.x * blockDim.x + threadIdx.x;
    if (i < BATCH * ACT_DIM) q[i] = bq[i % ACT_DIM];
}

__device__ __forceinline__ float tanh_approx(float x) {
    float r;
    asm("tanh.approx.f32 %0, %1;" : "=f"(r) : "f"(x));
    return r;
}

// Fused MPN step + Hebbian update + q-head. R8 warp body verbatim; ONLY the
// grid order is swapped to hbase-fastest: consecutive CTAs cover consecutive
// 8KB slices of the same M batch row, so the ~1000 in-flight CTAs sweep a
// contiguous multi-MB window (DRAM row-buffer friendly) instead of 1000
// scattered 8KB windows at 512KB stride. W/obs reuse moves from L1 to L2,
// which has 60% headroom; the bet is spent where the kernel is bound (DRAM).
__global__ __launch_bounds__(256) void mpn_step_kernel(
    const float* __restrict__ obs,
    const float* __restrict__ M,
    const float* __restrict__ W,
    const float* __restrict__ bh,
    const float* __restrict__ Wq,
    float* __restrict__ newM,
    float* __restrict__ q)
{
    __shared__ float hsh[8];            // hv per warp

    const int hbase = blockIdx.x * 8;   // hbase-fastest: contiguous M sweep
    const int b     = blockIdx.y;
    const int tid   = threadIdx.x;
    const int warp  = tid >> 5;
    const int lane  = tid & 31;
    const int h     = hbase + warp;

    const float4* xp = reinterpret_cast<const float4*>(obs + (size_t)b * OBS_DIM);
    const float4* wp = reinterpret_cast<const float4*>(W + (size_t)h * OBS_DIM);
    const float4* Mrow = reinterpret_cast<const float4*>(
        M + ((size_t)b * HID_DIM + h) * OBS_DIM);

    // Independent loads, issued back-to-back: M streams (evict-first),
    // W/obs cache-resident.
    const float4 m0 = __ldcs(Mrow + lane);
    const float4 m1 = __ldcs(Mrow + lane + 32);
    const float4 w0 = __ldg(wp + lane);
    const float4 w1 = __ldg(wp + lane + 32);
    const float4 x0 = __ldg(xp + lane);
    const float4 x1 = __ldg(xp + lane + 32);

    // sum_o W[h,o] * obs[b,o] * (1 + M[b,h,o])
    float acc =
        w0.x * x0.x * (1.0f + m0.x) + w0.y * x0.y * (1.0f + m0.y) +
        w0.z * x0.z * (1.0f + m0.z) + w0.w * x0.w * (1.0f + m0.w) +
        w1.x * x1.x * (1.0f + m1.x) + w1.y * x1.y * (1.0f + m1.y) +
        w1.z * x1.z * (1.0f + m1.z) + w1.w * x1.w * (1.0f + m1.w);

    #pragma unroll
    for (int o = 16; o; o >>= 1)
        acc += __shfl_xor_sync(0xffffffffu, acc, o);

    const float hv = tanh_approx(acc + __ldg(bh + h));
    const float eh = ETA * hv;

    float4 n0, n1;
    n0.x = LAMBDA * m0.x + eh * x0.x;  n0.y = LAMBDA * m0.y + eh * x0.y;
    n0.z = LAMBDA * m0.z + eh * x0.z;  n0.w = LAMBDA * m0.w + eh * x0.w;
    n1.x = LAMBDA * m1.x + eh * x1.x;  n1.y = LAMBDA * m1.y + eh * x1.y;
    n1.z = LAMBDA * m1.z + eh * x1.z;  n1.w = LAMBDA * m1.w + eh * x1.w;

    float4* out = reinterpret_cast<float4*>(
        newM + ((size_t)b * HID_DIM + h) * OBS_DIM);
    __stcs(out + lane,      n0);
    __stcs(out + lane + 32, n1);

    if (lane == 0) hsh[warp] = hv;

    if (warp != 0) {
        // Producers: signal and retire. No blocking wait.
        asm volatile("bar.arrive 1, 256;");
        return;
    }
    asm volatile("bar.sync 1, 256;");

    // q-head epilogue: warp 0 reduces this block's 8 h-rows, 18 REDs total.
    if (lane < ACT_DIM) {
        const float4* wq = reinterpret_cast<const float4*>(
            Wq + (size_t)lane * HID_DIM + hbase);
        const float4 a0 = __ldg(wq);      // L2-resident (36 KB total)
        const float4 a1 = __ldg(wq + 1);
        const float qv = a0.x * hsh[0] + a0.y * hsh[1]
                       + a0.z * hsh[2] + a0.w * hsh[3]
                       + a1.x * hsh[4] + a1.y * hsh[5]
                       + a1.z * hsh[6] + a1.w * hsh[7];
        atomicAdd(q + (size_t)b * ACT_DIM + lane, qv);
    }
}

extern "C" void kernel_launch(void* const* d_in, const int* in_sizes, int n_in,
                              void* d_out, int out_size) {
    const float* obs = (const float*)d_in[0];  // [1024, 256]
    const float* M   = (const float*)d_in[1];  // [1024, 512, 256]
    const float* W   = (const float*)d_in[2];  // [512, 256]
    const float* bh  = (const float*)d_in[3];  // [512]
    const float* Wq  = (const float*)d_in[4];  // [18, 512]
    const float* bq  = (const float*)d_in[5];  // [18]

    float* q    = (float*)d_out;               // [1024, 18]
    float* newM = q + (size_t)BATCH * ACT_DIM; // [1024, 512, 256]

    q_init_kernel<<<(BATCH * ACT_DIM + 255) / 256, 256>>>(bq, q);

    dim3 grid(HID_DIM / 8, BATCH);             // hbase-fastest: contiguous M
    mpn_step_kernel<<<grid, 256>>>(obs, M, W, bh, Wq, newM, q);
}